// round 2
// baseline (speedup 1.0000x reference)
#include <cuda_runtime.h>
#include <cuda_bf16.h>
#include <cstdint>

// Problem constants
#define BB 4
#define NN 10000
#define EE 170000
#define F_IN 256
#define FF 128
#define HH 4
#define MROWS (BB * NN)      // 40000
#define CCOLS (HH * FF)      // 512
#define NODE_STRIDE (BB * HH * FF)  // 2048 floats per node in h scratch

// Scratch (device globals; no allocation allowed)
__device__ float g_h[(size_t)NN * NODE_STRIDE];   // h[n][b][hi][f]  (81.92 MB)
__device__ float g_ps[HH * NN];                   // p_src[hi][n]
__device__ float g_pd[HH * NN];                   // p_dst[hi][n]
__device__ int   g_rowstart[NN + 1];

// ---------------------------------------------------------------------------
// Kernel 1: h[n][b][hi][f] = sum_k x[b,n,k] * W_mlp[hi,k,f] + b_mlp[hi,f]
// Tiled FP32 GEMM: M=40000 (m = b*N+n), C=512 (c = hi*F+f), K=256.
// BM=64, BN=64, BK=16, 256 threads, 4x4 per thread.
// ---------------------------------------------------------------------------
__global__ __launch_bounds__(256) void gemm_kernel(
    const float* __restrict__ x,     // [B][N][F_IN]
    const float* __restrict__ W,     // [H][F_IN][F]
    const float* __restrict__ bias)  // [H][F]
{
    __shared__ float As[16][64];
    __shared__ float Bs[16][64];

    const int tid = threadIdx.x;
    const int tx = tid & 15;
    const int ty = tid >> 4;
    const int m0 = blockIdx.x * 64;
    const int c0 = blockIdx.y * 64;      // 64 | 128 -> block stays within one head
    const int hi = c0 >> 7;
    const int f0 = c0 & 127;

    float acc[4][4];
    #pragma unroll
    for (int i = 0; i < 4; i++)
        #pragma unroll
        for (int j = 0; j < 4; j++) acc[i][j] = 0.f;

    const int arow = tid >> 2;           // 0..63
    const int akk  = (tid & 3) * 4;      // 0,4,8,12
    const int brow = tid >> 4;           // 0..15 (k within tile)
    const int bcc  = (tid & 15) * 4;     // 0..60

    for (int k0 = 0; k0 < F_IN; k0 += 16) {
        float4 av = *(const float4*)(x + (size_t)(m0 + arow) * F_IN + k0 + akk);
        As[akk + 0][arow] = av.x;
        As[akk + 1][arow] = av.y;
        As[akk + 2][arow] = av.z;
        As[akk + 3][arow] = av.w;
        float4 bv = *(const float4*)(W + ((size_t)hi * F_IN + k0 + brow) * FF + f0 + bcc);
        *(float4*)&Bs[brow][bcc] = bv;
        __syncthreads();

        #pragma unroll
        for (int k = 0; k < 16; k++) {
            float4 aq = *(const float4*)&As[k][ty * 4];
            float4 bq = *(const float4*)&Bs[k][tx * 4];
            float a[4] = {aq.x, aq.y, aq.z, aq.w};
            float b[4] = {bq.x, bq.y, bq.z, bq.w};
            #pragma unroll
            for (int i = 0; i < 4; i++)
                #pragma unroll
                for (int j = 0; j < 4; j++)
                    acc[i][j] = fmaf(a[i], b[j], acc[i][j]);
        }
        __syncthreads();
    }

    // Epilogue: bias + store into h[n][b][hi][f]
    float4 bvq = *(const float4*)(bias + hi * FF + f0 + tx * 4);
    float bb[4] = {bvq.x, bvq.y, bvq.z, bvq.w};
    #pragma unroll
    for (int i = 0; i < 4; i++) {
        int m = m0 + ty * 4 + i;
        int b = m / NN;
        int n = m - b * NN;
        float* hp = g_h + (size_t)n * NODE_STRIDE + b * (HH * FF) + hi * FF + f0 + tx * 4;
        float4 v;
        v.x = acc[i][0] + bb[0];
        v.y = acc[i][1] + bb[1];
        v.z = acc[i][2] + bb[2];
        v.w = acc[i][3] + bb[3];
        *(float4*)hp = v;
    }
}

// ---------------------------------------------------------------------------
// Kernel 2: p_src[hi][n], p_dst[hi][n] from h[n][B-1][hi][:] dot W_attn
// grid = N, block = 128 (warp w handles head w)
// ---------------------------------------------------------------------------
__global__ __launch_bounds__(128) void pvec_kernel(const float* __restrict__ Wattn)
{
    const int n = blockIdx.x;
    const int w = threadIdx.x >> 5;      // head
    const int lane = threadIdx.x & 31;

    const float* hrow = g_h + (size_t)n * NODE_STRIDE + (BB - 1) * (HH * FF) + w * FF;
    const float* asrc = Wattn + w * (2 * FF);
    const float* adst = asrc + FF;

    float ss = 0.f, sd = 0.f;
    #pragma unroll
    for (int j = 0; j < 4; j++) {
        float hv = hrow[lane + 32 * j];
        ss = fmaf(hv, asrc[lane + 32 * j], ss);
        sd = fmaf(hv, adst[lane + 32 * j], sd);
    }
    #pragma unroll
    for (int o = 16; o > 0; o >>= 1) {
        ss += __shfl_down_sync(0xffffffffu, ss, o);
        sd += __shfl_down_sync(0xffffffffu, sd, o);
    }
    if (lane == 0) {
        g_ps[w * NN + n] = ss;
        g_pd[w * NN + n] = sd;
    }
}

// ---------------------------------------------------------------------------
// Kernel 3: row_start[n] = lower_bound(src, n)  (src is sorted)
// ---------------------------------------------------------------------------
__global__ void rowstart_kernel(const int* __restrict__ src)
{
    int n = blockIdx.x * blockDim.x + threadIdx.x;
    if (n > NN) return;
    int lo = 0, hi = EE;
    while (lo < hi) {
        int mid = (lo + hi) >> 1;
        if (src[mid] < n) lo = mid + 1; else hi = mid;
    }
    g_rowstart[n] = lo;
}

// ---------------------------------------------------------------------------
// Kernel 4: aggregation. One block per src node n.
// out[b][n][hi*F+f] = (1/denom[hi]) * sum_{e in node} ew[hi][e] * h[dst[e]][b][hi][f]
// ew = exp(clip(leaky_relu(p_src[hi][n] + p_dst[hi][dst[e]]), -2, 2))
// ---------------------------------------------------------------------------
#define CHUNK 128
__global__ __launch_bounds__(256) void agg_kernel(
    const int* __restrict__ dst,
    float* __restrict__ out)
{
    const int n = blockIdx.x;
    const int t = threadIdx.x;
    const int e0 = g_rowstart[n];
    const int e1 = g_rowstart[n + 1];

    const int base = t * 8;              // covers 2048 = B*H*F floats
    const int hi = (base >> 7) & 3;
    const int b  = base >> 9;

    __shared__ int   s_dst[CHUNK];
    __shared__ float s_w[HH][CHUNK];
    __shared__ float s_den[HH];

    float acc[8];
    #pragma unroll
    for (int j = 0; j < 8; j++) acc[j] = 0.f;
    float den_local = 0.f;               // valid for t < 4

    for (int cs = e0; cs < e1; cs += CHUNK) {
        const int m = min(cs + CHUNK, e1) - cs;
        if (t < m) {
            int e = cs + t;
            int d = dst[e];
            s_dst[t] = d;
            #pragma unroll
            for (int h = 0; h < HH; h++) {
                float s = g_ps[h * NN + n] + g_pd[h * NN + d];
                s = (s >= 0.f) ? s : 0.2f * s;
                s = fminf(fmaxf(s, -2.f), 2.f);
                s_w[h][t] = __expf(s);
            }
        }
        __syncthreads();

        if (t < HH) {
            float sm = 0.f;
            for (int e = 0; e < m; e++) sm += s_w[t][e];
            den_local += sm;
        }

        #pragma unroll 2
        for (int e = 0; e < m; e++) {
            float w = s_w[hi][e];
            const float4* hp = (const float4*)(g_h + (size_t)s_dst[e] * NODE_STRIDE + base);
            float4 v0 = hp[0];
            float4 v1 = hp[1];
            acc[0] = fmaf(w, v0.x, acc[0]);
            acc[1] = fmaf(w, v0.y, acc[1]);
            acc[2] = fmaf(w, v0.z, acc[2]);
            acc[3] = fmaf(w, v0.w, acc[3]);
            acc[4] = fmaf(w, v1.x, acc[4]);
            acc[5] = fmaf(w, v1.y, acc[5]);
            acc[6] = fmaf(w, v1.z, acc[6]);
            acc[7] = fmaf(w, v1.w, acc[7]);
        }
        __syncthreads();
    }

    if (t < HH) s_den[t] = den_local;
    __syncthreads();

    float inv = (e1 > e0) ? (1.f / s_den[hi]) : 0.f;
    float* op = out + ((size_t)b * NN + n) * CCOLS + (base & (CCOLS - 1));
    float4 o0, o1;
    o0.x = acc[0] * inv; o0.y = acc[1] * inv; o0.z = acc[2] * inv; o0.w = acc[3] * inv;
    o1.x = acc[4] * inv; o1.y = acc[5] * inv; o1.z = acc[6] * inv; o1.w = acc[7] * inv;
    ((float4*)op)[0] = o0;
    ((float4*)op)[1] = o1;
}

// ---------------------------------------------------------------------------
// Launch
// ---------------------------------------------------------------------------
extern "C" void kernel_launch(void* const* d_in, const int* in_sizes, int n_in,
                              void* d_out, int out_size)
{
    const float* x     = (const float*)d_in[0];  // (4,10000,256)
    const float* Wmlp  = (const float*)d_in[1];  // (4,256,128)
    const float* bmlp  = (const float*)d_in[2];  // (4,128)
    const float* Wattn = (const float*)d_in[3];  // (4,256,1)
    const int*   src   = (const int*)d_in[4];    // (170000)
    const int*   dst   = (const int*)d_in[5];    // (170000)
    float*       out   = (float*)d_out;          // (4,10000,512)

    (void)in_sizes; (void)n_in; (void)out_size;

    dim3 ggrid(MROWS / 64, CCOLS / 64);
    gemm_kernel<<<ggrid, 256>>>(x, Wmlp, bmlp);

    pvec_kernel<<<NN, 128>>>(Wattn);

    rowstart_kernel<<<(NN + 1 + 255) / 256, 256>>>(src);

    agg_kernel<<<NN, 256>>>(dst, out);
}

// round 4
// speedup vs baseline: 1.6887x; 1.6887x over previous
#include <cuda_runtime.h>
#include <cuda_bf16.h>
#include <cstdint>

// Problem constants
#define BB 4
#define NN 10000
#define EE 170000
#define F_IN 256
#define FF 128
#define HH 4
#define MROWS (BB * NN)             // 40000
#define CCOLS (HH * FF)             // 512
#define NODE_STRIDE (BB * HH * FF)  // 2048 floats per node
#define MTILES 313                  // ceil(40000/128)
#define MPAD (MTILES * 128)         // 40064

// Scratch (device globals; no allocation allowed)
__device__ float g_h[(size_t)NN * NODE_STRIDE];
__device__ float g_ps[HH * NN];
__device__ float g_pd[HH * NN];
__device__ int   g_rowstart[NN + 1];
// bf16 split images, row-major
__device__ __align__(16) __nv_bfloat16 g_Ahi[(size_t)MPAD * F_IN];
__device__ __align__(16) __nv_bfloat16 g_Alo[(size_t)MPAD * F_IN];
__device__ __align__(16) __nv_bfloat16 g_Bhi[HH * FF * F_IN];   // [head][f][k]
__device__ __align__(16) __nv_bfloat16 g_Blo[HH * FF * F_IN];

static __device__ __forceinline__ uint32_t smem_u32(const void* p) {
    uint32_t a;
    asm("{ .reg .u64 t; cvta.to.shared.u64 t, %1; cvt.u32.u64 %0, t; }" : "=r"(a) : "l"(p));
    return a;
}
static __device__ __forceinline__ void cp16(uint32_t dst, const void* src) {
    asm volatile("cp.async.cg.shared.global [%0], [%1], 16;" :: "r"(dst), "l"(src));
}
static __device__ __forceinline__ void ldm_x4(uint32_t& r0, uint32_t& r1, uint32_t& r2,
                                              uint32_t& r3, uint32_t addr) {
    asm volatile("ldmatrix.sync.aligned.m8n8.x4.shared.b16 {%0,%1,%2,%3}, [%4];"
                 : "=r"(r0), "=r"(r1), "=r"(r2), "=r"(r3) : "r"(addr));
}
static __device__ __forceinline__ void mma_bf16(float* c, const uint32_t* a, const uint32_t* b) {
    asm volatile(
        "mma.sync.aligned.m16n8k16.row.col.f32.bf16.bf16.f32 "
        "{%0,%1,%2,%3}, {%4,%5,%6,%7}, {%8,%9}, {%0,%1,%2,%3};"
        : "+f"(c[0]), "+f"(c[1]), "+f"(c[2]), "+f"(c[3])
        : "r"(a[0]), "r"(a[1]), "r"(a[2]), "r"(a[3]), "r"(b[0]), "r"(b[1]));
}

// ---------------------------------------------------------------------------
// Prep 1: split x (row-major [m][k]) into bf16 hi/lo. Pads m to MPAD with 0.
// ---------------------------------------------------------------------------
__global__ __launch_bounds__(256) void prep_x(const float* __restrict__ x)
{
    int idx = blockIdx.x * 256 + threadIdx.x;      // m*32 + kgroup
    if (idx >= MPAD * 32) return;
    int m  = idx >> 5;
    int kg = (idx & 31) << 3;

    float v[8];
    if (m < MROWS) {
        const float4* p = (const float4*)(x + (size_t)m * F_IN + kg);
        float4 a = p[0], b = p[1];
        v[0] = a.x; v[1] = a.y; v[2] = a.z; v[3] = a.w;
        v[4] = b.x; v[5] = b.y; v[6] = b.z; v[7] = b.w;
    } else {
        #pragma unroll
        for (int j = 0; j < 8; j++) v[j] = 0.f;
    }
    __nv_bfloat16 h8[8], l8[8];
    #pragma unroll
    for (int j = 0; j < 8; j++) {
        __nv_bfloat16 h = __float2bfloat16(v[j]);
        h8[j] = h;
        l8[j] = __float2bfloat16(v[j] - __bfloat162float(h));
    }
    *(uint4*)(g_Ahi + (size_t)m * F_IN + kg) = *(const uint4*)h8;
    *(uint4*)(g_Alo + (size_t)m * F_IN + kg) = *(const uint4*)l8;
}

// ---------------------------------------------------------------------------
// Prep 2: Bt[head][f][k] = W_mlp[head][k][f], bf16 hi/lo.
// ---------------------------------------------------------------------------
__global__ __launch_bounds__(256) void prep_w(const float* __restrict__ W)
{
    int idx = blockIdx.x * 256 + threadIdx.x;      // head*4096 + f*32 + kgroup
    if (idx >= HH * FF * 32) return;
    int head = idx >> 12;
    int f    = (idx >> 5) & 127;
    int kg   = (idx & 31) << 3;

    __nv_bfloat16 h8[8], l8[8];
    #pragma unroll
    for (int j = 0; j < 8; j++) {
        float v = W[(size_t)head * F_IN * FF + (size_t)(kg + j) * FF + f];
        __nv_bfloat16 h = __float2bfloat16(v);
        h8[j] = h;
        l8[j] = __float2bfloat16(v - __bfloat162float(h));
    }
    size_t o = ((size_t)head * FF + f) * F_IN + kg;
    *(uint4*)(g_Bhi + o) = *(const uint4*)h8;
    *(uint4*)(g_Blo + o) = *(const uint4*)l8;
}

// ---------------------------------------------------------------------------
// Tensor-core GEMM via mma.sync (bf16, fp32 accum), split-bf16 3-pass.
// Per CTA: 128 m-rows (tile), 128 n-cols (head). K=256 in 4 chunks of 64,
// cp.async double-buffered. 8 warps = 4(m) x 2(n); warp tile 32x64.
// smem stage: Ahi|Alo|Bhi|Blo, each [128][64] bf16, 8-chunk XOR swizzle.
// ---------------------------------------------------------------------------
#define BK 64
#define SUB_BYTES 16384            // 128 rows * 128 B
#define STAGE_BYTES 65536
#define GEMM_SMEM 131072

static __device__ __forceinline__ uint32_t sw_off(int row, int chunk) {
    return (uint32_t)(row * 128 + ((chunk ^ (row & 7)) << 4));
}

__global__ __launch_bounds__(256, 1) void gemm_mma(const float* __restrict__ bias)
{
    extern __shared__ __align__(16) unsigned char smem[];
    const uint32_t sb = smem_u32(smem);
    const int tid  = threadIdx.x;
    const int wid  = tid >> 5;
    const int lane = tid & 31;
    const int tile = blockIdx.x;
    const int head = blockIdx.y;

    const __nv_bfloat16* gsub[4];
    gsub[0] = g_Ahi + (size_t)tile * 128 * F_IN;
    gsub[1] = g_Alo + (size_t)tile * 128 * F_IN;
    gsub[2] = g_Bhi + (size_t)head * FF * F_IN;
    gsub[3] = g_Blo + (size_t)head * FF * F_IN;

    const int mw = wid & 3;        // m block (32 rows)
    const int nw = wid >> 2;       // n block (64 cols)

    float acc[2][8][4];
    #pragma unroll
    for (int i = 0; i < 2; i++)
        #pragma unroll
        for (int j = 0; j < 8; j++)
            #pragma unroll
            for (int q = 0; q < 4; q++) acc[i][j][q] = 0.f;

    // stage prefetch: 4 subtiles x 1024 16B units, 256 threads x 16
    auto prefetch = [&](int stage, int kc0) {
        uint32_t sdst = sb + stage * STAGE_BYTES;
        #pragma unroll
        for (int sub = 0; sub < 4; sub++) {
            #pragma unroll
            for (int i = 0; i < 4; i++) {
                int idx = tid + i * 256;           // 0..1023
                int row = idx >> 3;
                int ch  = idx & 7;
                cp16(sdst + sub * SUB_BYTES + sw_off(row, ch),
                     gsub[sub] + (size_t)row * F_IN + kc0 + ch * 8);
            }
        }
        asm volatile("cp.async.commit_group;" ::: "memory");
    };

    prefetch(0, 0);

    for (int c = 0; c < 4; c++) {
        if (c + 1 < 4) {
            prefetch((c + 1) & 1, (c + 1) * BK);
            asm volatile("cp.async.wait_group 1;" ::: "memory");
        } else {
            asm volatile("cp.async.wait_group 0;" ::: "memory");
        }
        __syncthreads();

        const uint32_t stb = sb + (c & 1) * STAGE_BYTES;
        // A ldmatrix lane addressing
        const int a_row = mw * 32 + (lane & 7) + ((lane >> 3 & 1) << 3);
        const int a_chx = lane >> 4;
        // B ldmatrix lane addressing
        const int b_row = nw * 64 + (lane & 7) + ((lane >> 4) << 3);
        const int b_chx = (lane >> 3) & 1;

        #pragma unroll
        for (int p = 0; p < 3; p++) {
            const uint32_t abase = stb + ((p == 2) ? SUB_BYTES : 0);
            const uint32_t bbase = stb + ((p == 1) ? 3 * SUB_BYTES : 2 * SUB_BYTES);
            #pragma unroll
            for (int ks = 0; ks < 4; ks++) {
                const int c0 = ks * 2;
                uint32_t a[2][4];
                #pragma unroll
                for (int mi = 0; mi < 2; mi++)
                    ldm_x4(a[mi][0], a[mi][1], a[mi][2], a[mi][3],
                           abase + sw_off(a_row + mi * 16, c0 + a_chx));
                uint32_t b[8][2];
                #pragma unroll
                for (int j = 0; j < 4; j++) {
                    uint32_t r0, r1, r2, r3;
                    ldm_x4(r0, r1, r2, r3,
                           bbase + sw_off(b_row + j * 16, c0 + b_chx));
                    b[2 * j][0] = r0; b[2 * j][1] = r1;
                    b[2 * j + 1][0] = r2; b[2 * j + 1][1] = r3;
                }
                #pragma unroll
                for (int mi = 0; mi < 2; mi++)
                    #pragma unroll
                    for (int ni = 0; ni < 8; ni++)
                        mma_bf16(acc[mi][ni], a[mi], b[ni]);
            }
        }
        __syncthreads();
    }

    // Epilogue: add bias, scatter to g_h[n][b][head][f]
    const int col0 = nw * 64 + 2 * (lane & 3);
    #pragma unroll
    for (int mi = 0; mi < 2; mi++) {
        const int rl = mw * 32 + mi * 16 + (lane >> 2);
        #pragma unroll
        for (int half = 0; half < 2; half++) {
            const int m = tile * 128 + rl + half * 8;
            if (m >= MROWS) continue;
            const int bidx = m / NN;
            const int n = m - bidx * NN;
            float* op = g_h + (size_t)n * NODE_STRIDE + bidx * (HH * FF) + head * FF;
            #pragma unroll
            for (int ni = 0; ni < 8; ni++) {
                const int col = col0 + ni * 8;
                float2 o;
                o.x = acc[mi][ni][half * 2 + 0] + bias[head * FF + col];
                o.y = acc[mi][ni][half * 2 + 1] + bias[head * FF + col + 1];
                *(float2*)(op + col) = o;
            }
        }
    }
}

// ---------------------------------------------------------------------------
// p_src / p_dst
// ---------------------------------------------------------------------------
__global__ __launch_bounds__(128) void pvec_kernel(const float* __restrict__ Wattn)
{
    const int n = blockIdx.x;
    const int w = threadIdx.x >> 5;
    const int lane = threadIdx.x & 31;

    const float* hrow = g_h + (size_t)n * NODE_STRIDE + (BB - 1) * (HH * FF) + w * FF;
    const float* asrc = Wattn + w * (2 * FF);
    const float* adst = asrc + FF;

    float ss = 0.f, sd = 0.f;
    #pragma unroll
    for (int j = 0; j < 4; j++) {
        float hv = hrow[lane + 32 * j];
        ss = fmaf(hv, asrc[lane + 32 * j], ss);
        sd = fmaf(hv, adst[lane + 32 * j], sd);
    }
    #pragma unroll
    for (int o = 16; o > 0; o >>= 1) {
        ss += __shfl_down_sync(0xffffffffu, ss, o);
        sd += __shfl_down_sync(0xffffffffu, sd, o);
    }
    if (lane == 0) {
        g_ps[w * NN + n] = ss;
        g_pd[w * NN + n] = sd;
    }
}

// ---------------------------------------------------------------------------
// row_start via binary search (src sorted)
// ---------------------------------------------------------------------------
__global__ void rowstart_kernel(const int* __restrict__ src)
{
    int n = blockIdx.x * blockDim.x + threadIdx.x;
    if (n > NN) return;
    int lo = 0, hi = EE;
    while (lo < hi) {
        int mid = (lo + hi) >> 1;
        if (src[mid] < n) lo = mid + 1; else hi = mid;
    }
    g_rowstart[n] = lo;
}

// ---------------------------------------------------------------------------
// Aggregation (one block per src node)
// ---------------------------------------------------------------------------
#define ACHUNK 128
__global__ __launch_bounds__(256) void agg_kernel(
    const int* __restrict__ dst,
    float* __restrict__ out)
{
    const int n = blockIdx.x;
    const int t = threadIdx.x;
    const int e0 = g_rowstart[n];
    const int e1 = g_rowstart[n + 1];

    const int base = t * 8;
    const int hi = (base >> 7) & 3;
    const int b  = base >> 9;

    __shared__ int   s_dst[ACHUNK];
    __shared__ float s_w[HH][ACHUNK];
    __shared__ float s_den[HH];

    float acc[8];
    #pragma unroll
    for (int j = 0; j < 8; j++) acc[j] = 0.f;
    float den_local = 0.f;

    for (int cs = e0; cs < e1; cs += ACHUNK) {
        const int m = min(cs + ACHUNK, e1) - cs;
        if (t < m) {
            int e = cs + t;
            int d = dst[e];
            s_dst[t] = d;
            #pragma unroll
            for (int h = 0; h < HH; h++) {
                float s = g_ps[h * NN + n] + g_pd[h * NN + d];
                s = (s >= 0.f) ? s : 0.2f * s;
                s = fminf(fmaxf(s, -2.f), 2.f);
                s_w[h][t] = __expf(s);
            }
        }
        __syncthreads();

        if (t < HH) {
            float sm = 0.f;
            for (int e = 0; e < m; e++) sm += s_w[t][e];
            den_local += sm;
        }

        #pragma unroll 2
        for (int e = 0; e < m; e++) {
            float w = s_w[hi][e];
            const float4* hp = (const float4*)(g_h + (size_t)s_dst[e] * NODE_STRIDE + base);
            float4 v0 = hp[0];
            float4 v1 = hp[1];
            acc[0] = fmaf(w, v0.x, acc[0]);
            acc[1] = fmaf(w, v0.y, acc[1]);
            acc[2] = fmaf(w, v0.z, acc[2]);
            acc[3] = fmaf(w, v0.w, acc[3]);
            acc[4] = fmaf(w, v1.x, acc[4]);
            acc[5] = fmaf(w, v1.y, acc[5]);
            acc[6] = fmaf(w, v1.z, acc[6]);
            acc[7] = fmaf(w, v1.w, acc[7]);
        }
        __syncthreads();
    }

    if (t < HH) s_den[t] = den_local;
    __syncthreads();

    float inv = (e1 > e0) ? (1.f / s_den[hi]) : 0.f;
    float* op = out + ((size_t)b * NN + n) * CCOLS + (base & (CCOLS - 1));
    float4 o0, o1;
    o0.x = acc[0] * inv; o0.y = acc[1] * inv; o0.z = acc[2] * inv; o0.w = acc[3] * inv;
    o1.x = acc[4] * inv; o1.y = acc[5] * inv; o1.z = acc[6] * inv; o1.w = acc[7] * inv;
    ((float4*)op)[0] = o0;
    ((float4*)op)[1] = o1;
}

// ---------------------------------------------------------------------------
// Launch
// ---------------------------------------------------------------------------
extern "C" void kernel_launch(void* const* d_in, const int* in_sizes, int n_in,
                              void* d_out, int out_size)
{
    const float* x     = (const float*)d_in[0];
    const float* Wmlp  = (const float*)d_in[1];
    const float* bmlp  = (const float*)d_in[2];
    const float* Wattn = (const float*)d_in[3];
    const int*   src   = (const int*)d_in[4];
    const int*   dst   = (const int*)d_in[5];
    float*       out   = (float*)d_out;

    (void)in_sizes; (void)n_in; (void)out_size;

    static int smem_set = 0;
    if (!smem_set) {
        cudaFuncSetAttribute(gemm_mma, cudaFuncAttributeMaxDynamicSharedMemorySize, GEMM_SMEM);
        smem_set = 1;
    }

    prep_x<<<(MPAD * 32 + 255) / 256, 256>>>(x);
    prep_w<<<(HH * FF * 32 + 255) / 256, 256>>>(Wmlp);

    gemm_mma<<<dim3(MTILES, HH), 256, GEMM_SMEM>>>(bmlp);

    pvec_kernel<<<NN, 128>>>(Wattn);
    rowstart_kernel<<<(NN + 1 + 255) / 256, 256>>>(src);
    agg_kernel<<<NN, 256>>>(dst, out);
}

// round 6
// speedup vs baseline: 2.0162x; 1.1940x over previous
#include <cuda_runtime.h>
#include <cuda_bf16.h>
#include <cuda_fp16.h>
#include <cstdint>

// Problem constants
#define BB 4
#define NN 10000
#define EE 170000
#define F_IN 256
#define FF 128
#define HH 4
#define MROWS (BB * NN)             // 40000
#define CCOLS (HH * FF)             // 512
#define NODE_STRIDE (BB * HH * FF)  // 2048 elements per node
#define MTILES 313                  // ceil(40000/128)
#define MPAD (MTILES * 128)         // 40064

// Scratch (device globals; no allocation allowed)
__device__ __align__(16) __half g_h16[(size_t)NN * NODE_STRIDE];  // fp16 h (41MB)
__device__ __align__(16) float g_hlast[(size_t)NN * CCOLS];       // fp32 h[batch B-1] (20MB)
__device__ float g_ps[HH * NN];
__device__ float g_pd[HH * NN];
__device__ int   g_rowstart[NN + 1];
// bf16 split images, row-major
__device__ __align__(16) __nv_bfloat16 g_Ahi[(size_t)MPAD * F_IN];
__device__ __align__(16) __nv_bfloat16 g_Alo[(size_t)MPAD * F_IN];
__device__ __align__(16) __nv_bfloat16 g_Bhi[HH * FF * F_IN];   // [head][f][k]
__device__ __align__(16) __nv_bfloat16 g_Blo[HH * FF * F_IN];

static __device__ __forceinline__ uint32_t smem_u32(const void* p) {
    uint32_t a;
    asm("{ .reg .u64 t; cvta.to.shared.u64 t, %1; cvt.u32.u64 %0, t; }" : "=r"(a) : "l"(p));
    return a;
}
static __device__ __forceinline__ void cp16(uint32_t dst, const void* src) {
    asm volatile("cp.async.cg.shared.global [%0], [%1], 16;" :: "r"(dst), "l"(src));
}
static __device__ __forceinline__ void ldm_x4(uint32_t& r0, uint32_t& r1, uint32_t& r2,
                                              uint32_t& r3, uint32_t addr) {
    asm volatile("ldmatrix.sync.aligned.m8n8.x4.shared.b16 {%0,%1,%2,%3}, [%4];"
                 : "=r"(r0), "=r"(r1), "=r"(r2), "=r"(r3) : "r"(addr));
}
static __device__ __forceinline__ void mma_bf16(float* c, const uint32_t* a, const uint32_t* b) {
    asm volatile(
        "mma.sync.aligned.m16n8k16.row.col.f32.bf16.bf16.f32 "
        "{%0,%1,%2,%3}, {%4,%5,%6,%7}, {%8,%9}, {%0,%1,%2,%3};"
        : "+f"(c[0]), "+f"(c[1]), "+f"(c[2]), "+f"(c[3])
        : "r"(a[0]), "r"(a[1]), "r"(a[2]), "r"(a[3]), "r"(b[0]), "r"(b[1]));
}

// ---------------------------------------------------------------------------
// Prep 1: split x (row-major [m][k]) into bf16 hi/lo. Pads m to MPAD with 0.
// ---------------------------------------------------------------------------
__global__ __launch_bounds__(256) void prep_x(const float* __restrict__ x)
{
    int idx = blockIdx.x * 256 + threadIdx.x;      // m*32 + kgroup
    if (idx >= MPAD * 32) return;
    int m  = idx >> 5;
    int kg = (idx & 31) << 3;

    float v[8];
    if (m < MROWS) {
        const float4* p = (const float4*)(x + (size_t)m * F_IN + kg);
        float4 a = p[0], b = p[1];
        v[0] = a.x; v[1] = a.y; v[2] = a.z; v[3] = a.w;
        v[4] = b.x; v[5] = b.y; v[6] = b.z; v[7] = b.w;
    } else {
        #pragma unroll
        for (int j = 0; j < 8; j++) v[j] = 0.f;
    }
    __nv_bfloat16 h8[8], l8[8];
    #pragma unroll
    for (int j = 0; j < 8; j++) {
        __nv_bfloat16 h = __float2bfloat16(v[j]);
        h8[j] = h;
        l8[j] = __float2bfloat16(v[j] - __bfloat162float(h));
    }
    *(uint4*)(g_Ahi + (size_t)m * F_IN + kg) = *(const uint4*)h8;
    *(uint4*)(g_Alo + (size_t)m * F_IN + kg) = *(const uint4*)l8;
}

// ---------------------------------------------------------------------------
// Prep 2: Bt[head][f][k] = W_mlp[head][k][f], bf16 hi/lo.
// ---------------------------------------------------------------------------
__global__ __launch_bounds__(256) void prep_w(const float* __restrict__ W)
{
    int idx = blockIdx.x * 256 + threadIdx.x;      // head*4096 + f*32 + kgroup
    if (idx >= HH * FF * 32) return;
    int head = idx >> 12;
    int f    = (idx >> 5) & 127;
    int kg   = (idx & 31) << 3;

    __nv_bfloat16 h8[8], l8[8];
    #pragma unroll
    for (int j = 0; j < 8; j++) {
        float v = W[(size_t)head * F_IN * FF + (size_t)(kg + j) * FF + f];
        __nv_bfloat16 h = __float2bfloat16(v);
        h8[j] = h;
        l8[j] = __float2bfloat16(v - __bfloat162float(h));
    }
    size_t o = ((size_t)head * FF + f) * F_IN + kg;
    *(uint4*)(g_Bhi + o) = *(const uint4*)h8;
    *(uint4*)(g_Blo + o) = *(const uint4*)l8;
}

// ---------------------------------------------------------------------------
// Tensor-core GEMM via mma.sync (bf16, fp32 accum), split-bf16 3-pass.
// grid = (4 heads, 313 m-tiles)  -- head fastest so the 4 CTAs sharing an
// A tile land in the same wave (A read once from DRAM, 3x from L2).
// Per CTA: 128m x 128n. K=256 in 4 chunks of 64, cp.async double-buffered.
// 8 warps = 4(m) x 2(n); warp tile 32x64.
// ---------------------------------------------------------------------------
#define BK 64
#define SUB_BYTES 16384            // 128 rows * 128 B
#define STAGE_BYTES 65536
#define GEMM_SMEM 131072

static __device__ __forceinline__ uint32_t sw_off(int row, int chunk) {
    return (uint32_t)(row * 128 + ((chunk ^ (row & 7)) << 4));
}

__global__ __launch_bounds__(256, 1) void gemm_mma(const float* __restrict__ bias)
{
    extern __shared__ __align__(16) unsigned char smem[];
    const uint32_t sb = smem_u32(smem);
    const int tid  = threadIdx.x;
    const int wid  = tid >> 5;
    const int lane = tid & 31;
    const int head = blockIdx.x;
    const int tile = blockIdx.y;

    const __nv_bfloat16* gsub[4];
    gsub[0] = g_Ahi + (size_t)tile * 128 * F_IN;
    gsub[1] = g_Alo + (size_t)tile * 128 * F_IN;
    gsub[2] = g_Bhi + (size_t)head * FF * F_IN;
    gsub[3] = g_Blo + (size_t)head * FF * F_IN;

    const int mw = wid & 3;        // m block (32 rows)
    const int nw = wid >> 2;       // n block (64 cols)

    float acc[2][8][4];
    #pragma unroll
    for (int i = 0; i < 2; i++)
        #pragma unroll
        for (int j = 0; j < 8; j++)
            #pragma unroll
            for (int q = 0; q < 4; q++) acc[i][j][q] = 0.f;

    auto prefetch = [&](int stage, int kc0) {
        uint32_t sdst = sb + stage * STAGE_BYTES;
        #pragma unroll
        for (int sub = 0; sub < 4; sub++) {
            #pragma unroll
            for (int i = 0; i < 4; i++) {
                int idx = tid + i * 256;           // 0..1023
                int row = idx >> 3;
                int ch  = idx & 7;
                cp16(sdst + sub * SUB_BYTES + sw_off(row, ch),
                     gsub[sub] + (size_t)row * F_IN + kc0 + ch * 8);
            }
        }
        asm volatile("cp.async.commit_group;" ::: "memory");
    };

    prefetch(0, 0);

    for (int c = 0; c < 4; c++) {
        if (c + 1 < 4) {
            prefetch((c + 1) & 1, (c + 1) * BK);
            asm volatile("cp.async.wait_group 1;" ::: "memory");
        } else {
            asm volatile("cp.async.wait_group 0;" ::: "memory");
        }
        __syncthreads();

        const uint32_t stb = sb + (c & 1) * STAGE_BYTES;
        const int a_row = mw * 32 + (lane & 7) + ((lane >> 3 & 1) << 3);
        const int a_chx = lane >> 4;
        const int b_row = nw * 64 + (lane & 7) + ((lane >> 4) << 3);
        const int b_chx = (lane >> 3) & 1;

        #pragma unroll
        for (int p = 0; p < 3; p++) {
            const uint32_t abase = stb + ((p == 2) ? SUB_BYTES : 0);
            const uint32_t bbase = stb + ((p == 1) ? 3 * SUB_BYTES : 2 * SUB_BYTES);
            #pragma unroll
            for (int ks = 0; ks < 4; ks++) {
                const int c0 = ks * 2;
                uint32_t a[2][4];
                #pragma unroll
                for (int mi = 0; mi < 2; mi++)
                    ldm_x4(a[mi][0], a[mi][1], a[mi][2], a[mi][3],
                           abase + sw_off(a_row + mi * 16, c0 + a_chx));
                uint32_t b[8][2];
                #pragma unroll
                for (int j = 0; j < 4; j++) {
                    uint32_t r0, r1, r2, r3;
                    ldm_x4(r0, r1, r2, r3,
                           bbase + sw_off(b_row + j * 16, c0 + b_chx));
                    b[2 * j][0] = r0; b[2 * j][1] = r1;
                    b[2 * j + 1][0] = r2; b[2 * j + 1][1] = r3;
                }
                #pragma unroll
                for (int mi = 0; mi < 2; mi++)
                    #pragma unroll
                    for (int ni = 0; ni < 8; ni++)
                        mma_bf16(acc[mi][ni], a[mi], b[ni]);
            }
        }
        __syncthreads();
    }

    // Epilogue: add bias; write fp16 h (for agg) + fp32 last-batch h (for pvec)
    const int col0 = nw * 64 + 2 * (lane & 3);
    #pragma unroll
    for (int mi = 0; mi < 2; mi++) {
        const int rl = mw * 32 + mi * 16 + (lane >> 2);
        #pragma unroll
        for (int half = 0; half < 2; half++) {
            const int m = tile * 128 + rl + half * 8;
            if (m >= MROWS) continue;
            const int bidx = m / NN;
            const int n = m - bidx * NN;
            __half* op16 = g_h16 + (size_t)n * NODE_STRIDE + bidx * (HH * FF) + head * FF;
            float* opl = g_hlast + (size_t)n * CCOLS + head * FF;
            #pragma unroll
            for (int ni = 0; ni < 8; ni++) {
                const int col = col0 + ni * 8;
                float ox = acc[mi][ni][half * 2 + 0] + bias[head * FF + col];
                float oy = acc[mi][ni][half * 2 + 1] + bias[head * FF + col + 1];
                *(__half2*)(op16 + col) = __floats2half2_rn(ox, oy);
                if (bidx == BB - 1) {
                    float2 o; o.x = ox; o.y = oy;
                    *(float2*)(opl + col) = o;
                }
            }
        }
    }
}

// ---------------------------------------------------------------------------
// p_src / p_dst from fp32 last-batch h
// ---------------------------------------------------------------------------
__global__ __launch_bounds__(128) void pvec_kernel(const float* __restrict__ Wattn)
{
    const int n = blockIdx.x;
    const int w = threadIdx.x >> 5;
    const int lane = threadIdx.x & 31;

    const float* hrow = g_hlast + (size_t)n * CCOLS + w * FF;
    const float* asrc = Wattn + w * (2 * FF);
    const float* adst = asrc + FF;

    float ss = 0.f, sd = 0.f;
    #pragma unroll
    for (int j = 0; j < 4; j++) {
        float hv = hrow[lane + 32 * j];
        ss = fmaf(hv, asrc[lane + 32 * j], ss);
        sd = fmaf(hv, adst[lane + 32 * j], sd);
    }
    #pragma unroll
    for (int o = 16; o > 0; o >>= 1) {
        ss += __shfl_down_sync(0xffffffffu, ss, o);
        sd += __shfl_down_sync(0xffffffffu, sd, o);
    }
    if (lane == 0) {
        g_ps[w * NN + n] = ss;
        g_pd[w * NN + n] = sd;
    }
}

// ---------------------------------------------------------------------------
// row_start via binary search (src sorted)
// ---------------------------------------------------------------------------
__global__ void rowstart_kernel(const int* __restrict__ src)
{
    int n = blockIdx.x * blockDim.x + threadIdx.x;
    if (n > NN) return;
    int lo = 0, hi = EE;
    while (lo < hi) {
        int mid = (lo + hi) >> 1;
        if (src[mid] < n) lo = mid + 1; else hi = mid;
    }
    g_rowstart[n] = lo;
}

// ---------------------------------------------------------------------------
// Aggregation (one block per src node). h gathered in fp16 (half traffic),
// accumulated fp32.
// ---------------------------------------------------------------------------
#define ACHUNK 128
__global__ __launch_bounds__(256) void agg_kernel(
    const int* __restrict__ dst,
    float* __restrict__ out)
{
    const int n = blockIdx.x;
    const int t = threadIdx.x;
    const int e0 = g_rowstart[n];
    const int e1 = g_rowstart[n + 1];

    const int base = t * 8;              // 2048 elems = 256 threads * 8
    const int hi = (base >> 7) & 3;
    const int b  = base >> 9;

    __shared__ int   s_dst[ACHUNK];
    __shared__ float s_w[HH][ACHUNK];
    __shared__ float s_den[HH];

    float acc[8];
    #pragma unroll
    for (int j = 0; j < 8; j++) acc[j] = 0.f;
    float den_local = 0.f;

    for (int cs = e0; cs < e1; cs += ACHUNK) {
        const int m = min(cs + ACHUNK, e1) - cs;
        if (t < m) {
            int e = cs + t;
            int d = dst[e];
            s_dst[t] = d;
            #pragma unroll
            for (int h = 0; h < HH; h++) {
                float s = g_ps[h * NN + n] + g_pd[h * NN + d];
                s = (s >= 0.f) ? s : 0.2f * s;
                s = fminf(fmaxf(s, -2.f), 2.f);
                s_w[h][t] = __expf(s);
            }
        }
        __syncthreads();

        if (t < HH) {
            float sm = 0.f;
            for (int e = 0; e < m; e++) sm += s_w[t][e];
            den_local += sm;
        }

        #pragma unroll 2
        for (int e = 0; e < m; e++) {
            float w = s_w[hi][e];
            uint4 v = *(const uint4*)(g_h16 + (size_t)s_dst[e] * NODE_STRIDE + base);
            float2 f0 = __half22float2(*reinterpret_cast<__half2*>(&v.x));
            float2 f1 = __half22float2(*reinterpret_cast<__half2*>(&v.y));
            float2 f2 = __half22float2(*reinterpret_cast<__half2*>(&v.z));
            float2 f3 = __half22float2(*reinterpret_cast<__half2*>(&v.w));
            acc[0] = fmaf(w, f0.x, acc[0]);
            acc[1] = fmaf(w, f0.y, acc[1]);
            acc[2] = fmaf(w, f1.x, acc[2]);
            acc[3] = fmaf(w, f1.y, acc[3]);
            acc[4] = fmaf(w, f2.x, acc[4]);
            acc[5] = fmaf(w, f2.y, acc[5]);
            acc[6] = fmaf(w, f3.x, acc[6]);
            acc[7] = fmaf(w, f3.y, acc[7]);
        }
        __syncthreads();
    }

    if (t < HH) s_den[t] = den_local;
    __syncthreads();

    float inv = (e1 > e0) ? (1.f / s_den[hi]) : 0.f;
    float* op = out + ((size_t)b * NN + n) * CCOLS + (base & (CCOLS - 1));
    float4 o0, o1;
    o0.x = acc[0] * inv; o0.y = acc[1] * inv; o0.z = acc[2] * inv; o0.w = acc[3] * inv;
    o1.x = acc[4] * inv; o1.y = acc[5] * inv; o1.z = acc[6] * inv; o1.w = acc[7] * inv;
    ((float4*)op)[0] = o0;
    ((float4*)op)[1] = o1;
}

// ---------------------------------------------------------------------------
// Launch
// ---------------------------------------------------------------------------
extern "C" void kernel_launch(void* const* d_in, const int* in_sizes, int n_in,
                              void* d_out, int out_size)
{
    const float* x     = (const float*)d_in[0];
    const float* Wmlp  = (const float*)d_in[1];
    const float* bmlp  = (const float*)d_in[2];
    const float* Wattn = (const float*)d_in[3];
    const int*   src   = (const int*)d_in[4];
    const int*   dst   = (const int*)d_in[5];
    float*       out   = (float*)d_out;

    (void)in_sizes; (void)n_in; (void)out_size;

    static int smem_set = 0;
    if (!smem_set) {
        cudaFuncSetAttribute(gemm_mma, cudaFuncAttributeMaxDynamicSharedMemorySize, GEMM_SMEM);
        smem_set = 1;
    }

    prep_x<<<(MPAD * 32 + 255) / 256, 256>>>(x);
    prep_w<<<(HH * FF * 32 + 255) / 256, 256>>>(Wmlp);

    gemm_mma<<<dim3(HH, MTILES), 256, GEMM_SMEM>>>(bmlp);

    pvec_kernel<<<NN, 128>>>(Wattn);
    rowstart_kernel<<<(NN + 1 + 255) / 256, 256>>>(src);
    agg_kernel<<<NN, 256>>>(dst, out);
}